// round 14
// baseline (speedup 1.0000x reference)
#include <cuda_runtime.h>
#include <cuda_bf16.h>

// x: [B=16, C=64, H=256, W=256] fp32; conv_w [1,2,7,7]; conv_b [1]
// out = x * sigmoid(conv7x7(concat(mean_c(x), max_c(x))) + b)
//
// 3-stage chunk pipeline, chunk = 2 batches (32 MB). Launch j runs
//   reduce(chunk j) || conv(chunk j-1) || mul(chunk j-2)
// with roles INTERLEAVED across blockIdx (groups of 13: 4 red, 1 conv,
// 8 mul) so every wave drives the DRAM read and write streams together.
// L2 window = 3 chunks = 96 MB < 126 MB, so x hits DRAM exactly once.

#define B 16
#define C 64
#define HW 65536           // 256*256
#define HWf4 16384         // HW/4
#define PLANE (C * HW)     // 2^22 elements (16 MB)
#define NBCH 2             // batches per chunk (32 MB)
#define NCHUNK (B / NBCH)  // 8

#define NGRP 128
#define TOT_BLKS (13 * NGRP)   // 1664: 512 red + 128 conv + 1024 mul

__device__ float g_att[B * 2 * HW];   // [b][{avg,max}][hw]
__device__ float g_s[B * HW];

__device__ __forceinline__ void f4add(float4& a, const float4 b) {
    a.x += b.x; a.y += b.y; a.z += b.z; a.w += b.w;
}
__device__ __forceinline__ void f4max(float4& a, const float4 b) {
    a.x = fmaxf(a.x, b.x); a.y = fmaxf(a.y, b.y);
    a.z = fmaxf(a.z, b.z); a.w = fmaxf(a.w, b.w);
}

__global__ void __launch_bounds__(256)
k_step(const float* __restrict__ x,
       const float* __restrict__ cw,
       const float* __restrict__ cb,
       float* __restrict__ out,
       int br0, int bc0, int bm0) {     // first batch of each role's chunk, -1 = skip
    const int grp  = blockIdx.x / 13;
    const int slot = blockIdx.x - grp * 13;
    const int tid  = threadIdx.x;

    if (slot < 4) {
        // ============ reduce(chunk br0): channel mean+max ============
        if (br0 < 0) return;
        const int rb = grp * 4 + slot;           // [0, 512)
        __shared__ float4 ssum[4][64];
        __shared__ float4 smax[4][64];

        const int px = tid & 63;
        const int g  = tid >> 6;                 // 0..3
        const int id = rb * 64 + px;             // [0, NBCH*HWf4)
        const int b  = br0 + (id >> 14);
        const int q4 = id & (HWf4 - 1);

        const float4* xb = reinterpret_cast<const float4*>(x + (size_t)b * PLANE);
        const int c0 = g * 16;

        float4 sum = xb[(size_t)c0 * HWf4 + q4];     // default cache: stay in L2
        float4 mx  = sum;
#pragma unroll
        for (int c = 1; c < 16; c++) {
            float4 v = xb[(size_t)(c0 + c) * HWf4 + q4];
            f4add(sum, v);
            f4max(mx, v);
        }
        ssum[g][px] = sum;
        smax[g][px] = mx;
        __syncthreads();

        if (g == 0) {
            float4 s = ssum[0][px], m = smax[0][px];
#pragma unroll
            for (int gg = 1; gg < 4; gg++) {
                f4add(s, ssum[gg][px]);
                f4max(m, smax[gg][px]);
            }
            const float inv = 1.0f / 64.0f;
            float4* avg_out = reinterpret_cast<float4*>(g_att + (size_t)b * 2 * HW);
            float4* max_out = reinterpret_cast<float4*>(g_att + (size_t)b * 2 * HW + HW);
            avg_out[q4] = make_float4(s.x * inv, s.y * inv, s.z * inv, s.w * inv);
            max_out[q4] = m;
        }

    } else if (slot == 4) {
        // ============ conv(chunk bc0): 7x7 + bias + sigmoid ============
        if (bc0 < 0) return;
        __shared__ float s_avg[22 * 72];
        __shared__ float s_mx[22 * 72];
        __shared__ float s_w[98];
        __shared__ float s_b;

        const int idx = grp;                     // [0, 128)
        const int b   = bc0 + (idx >> 6);
        const int t   = idx & 63;
        const int w0  = (t & 3) * 64;
        const int h0  = (t >> 2) * 16;

        if (tid < 98) s_w[tid] = cw[tid];
        if (tid == 98) s_b = cb[0];

        const float* avgp = g_att + (size_t)b * 2 * HW;
        const float* maxp = avgp + HW;

        for (int i = tid; i < 22 * 70; i += 256) {
            int dy = i / 70, dx = i - dy * 70;
            int hh = h0 - 3 + dy, ww = w0 - 3 + dx;
            float a = 0.f, m = 0.f;
            if (hh >= 0 && hh < 256 && ww >= 0 && ww < 256) {
                int ii = hh * 256 + ww;
                a = avgp[ii];
                m = maxp[ii];
            }
            s_avg[dy * 72 + dx] = a;
            s_mx[dy * 72 + dx]  = m;
        }
        __syncthreads();

        const int tx = tid & 15;
        const int ty = tid >> 4;
        const int ow0 = tx * 4;

        float a0 = s_b, a1 = a0, a2 = a0, a3 = a0;
#pragma unroll
        for (int kh = 0; kh < 7; kh++) {
            const float* ra = s_avg + (ty + kh) * 72 + ow0;
            const float* rm = s_mx  + (ty + kh) * 72 + ow0;
            float v[10];
#pragma unroll
            for (int j = 0; j < 10; j++) v[j] = ra[j];
#pragma unroll
            for (int kw = 0; kw < 7; kw++) {
                float wA = s_w[kh * 7 + kw];
                a0 = fmaf(wA, v[kw],     a0);
                a1 = fmaf(wA, v[kw + 1], a1);
                a2 = fmaf(wA, v[kw + 2], a2);
                a3 = fmaf(wA, v[kw + 3], a3);
            }
#pragma unroll
            for (int j = 0; j < 10; j++) v[j] = rm[j];
#pragma unroll
            for (int kw = 0; kw < 7; kw++) {
                float wM = s_w[49 + kh * 7 + kw];
                a0 = fmaf(wM, v[kw],     a0);
                a1 = fmaf(wM, v[kw + 1], a1);
                a2 = fmaf(wM, v[kw + 2], a2);
                a3 = fmaf(wM, v[kw + 3], a3);
            }
        }
        float4 sg;
        sg.x = 1.0f / (1.0f + __expf(-a0));
        sg.y = 1.0f / (1.0f + __expf(-a1));
        sg.z = 1.0f / (1.0f + __expf(-a2));
        sg.w = 1.0f / (1.0f + __expf(-a3));
        *reinterpret_cast<float4*>(g_s + (size_t)b * HW + (h0 + ty) * 256 + w0 + ow0) = sg;

    } else {
        // ============ mul(chunk bm0): out = x * s, 8 f4/thread ============
        if (bm0 < 0) return;
        const int mblk = grp * 8 + (slot - 5);   // [0, 1024)
        const size_t base = ((size_t)bm0 << 20) + (size_t)mblk * 2048 + tid;
        const int b = (int)(base >> 20);         // 2048*256-span stays in one batch

        const float4* xf = reinterpret_cast<const float4*>(x);
        float4* of = reinterpret_cast<float4*>(out);
        const float4* sb = reinterpret_cast<const float4*>(g_s + (size_t)b * HW);

        float4 xv[8], sv[8];
#pragma unroll
        for (int k = 0; k < 8; k++) xv[k] = __ldcs(xf + base + k * 256);   // L2 hit, evict after
#pragma unroll
        for (int k = 0; k < 8; k++) {
            int q4 = (int)((base + k * 256) & (HWf4 - 1));
            sv[k] = __ldg(sb + q4);
        }
#pragma unroll
        for (int k = 0; k < 8; k++) {
            xv[k].x *= sv[k].x; xv[k].y *= sv[k].y;
            xv[k].z *= sv[k].z; xv[k].w *= sv[k].w;
            __stcs(of + base + k * 256, xv[k]);            // stream out
        }
    }
}

// ---------------------------------------------------------------------------
extern "C" void kernel_launch(void* const* d_in, const int* in_sizes, int n_in,
                              void* d_out, int out_size) {
    const float* x  = (const float*)d_in[0];
    const float* cw = (const float*)d_in[1];
    const float* cb = (const float*)d_in[2];
    float* out = (float*)d_out;

    for (int j = 0; j < NCHUNK + 2; j++) {
        int br0 = (j < NCHUNK)                ? j * NBCH       : -1;
        int bc0 = (j >= 1 && j - 1 < NCHUNK)  ? (j - 1) * NBCH : -1;
        int bm0 = (j >= 2 && j - 2 < NCHUNK)  ? (j - 2) * NBCH : -1;
        k_step<<<TOT_BLKS, 256>>>(x, cw, cb, out, br0, bc0, bm0);
    }
}

// round 15
// speedup vs baseline: 1.0451x; 1.0451x over previous
#include <cuda_runtime.h>
#include <cuda_bf16.h>

// x: [B=16, C=64, H=256, W=256] fp32; conv_w [1,2,7,7]; conv_b [1]
// out = x * sigmoid(conv7x7(concat(mean_c(x), max_c(x))) + b)
//
// 3-kernel pipeline:
//  K1 reduce: channel mean+max (256 MB read @ ~82% ceiling)
//  K2 conv:   7x7 + bias + sigmoid (tiny, register sliding window)
//  K3 mul:    channel-reuse mapping — block = 256 f4-pixels x 16 channels,
//             s loaded ONCE per thread, x streamed in 8-deep batches.

#define B 16
#define C 64
#define HW 65536           // 256*256
#define HWf4 16384         // HW/4
#define PLANE (C * HW)     // 2^22 elements (16 MB)

__device__ float g_att[B * 2 * HW];   // [b][{avg,max}][hw]
__device__ float g_s[B * HW];

// ---------------------------------------------------------------------------
// K1: per-pixel channel mean+max. One thread = one float4-pixel, 64 channels.
// ---------------------------------------------------------------------------
__global__ void __launch_bounds__(256)
k_reduce(const float* __restrict__ x) {
    int t = blockIdx.x * blockDim.x + threadIdx.x;        // [0, B*HWf4)
    int b  = t >> 14;
    int q4 = t & (HWf4 - 1);

    const float4* xb = reinterpret_cast<const float4*>(x + (size_t)b * PLANE);

    float4 v = __ldcs(xb + q4);                            // c = 0
    float sx = v.x, sy = v.y, sz = v.z, sw = v.w;
    float mx = v.x, my = v.y, mz = v.z, mw = v.w;

#pragma unroll 8
    for (int c = 1; c < C; c++) {
        float4 u = __ldcs(xb + (size_t)c * HWf4 + q4);
        sx += u.x; sy += u.y; sz += u.z; sw += u.w;
        mx = fmaxf(mx, u.x); my = fmaxf(my, u.y);
        mz = fmaxf(mz, u.z); mw = fmaxf(mw, u.w);
    }

    const float inv = 1.0f / 64.0f;
    float4* avg_out = reinterpret_cast<float4*>(g_att + (size_t)b * 2 * HW);
    float4* max_out = reinterpret_cast<float4*>(g_att + (size_t)b * 2 * HW + HW);
    avg_out[q4] = make_float4(sx * inv, sy * inv, sz * inv, sw * inv);
    max_out[q4] = make_float4(mx, my, mz, mw);
}

// ---------------------------------------------------------------------------
// K2: 7x7 conv + bias + sigmoid -> g_s. 64x16 tile, register sliding window.
// Grid: (4, 16, B), 256 threads. Thread owns 4 outputs in w.
// ---------------------------------------------------------------------------
__global__ void __launch_bounds__(256)
k_conv(const float* __restrict__ cw, const float* __restrict__ cb) {
    __shared__ float s_avg[22 * 72];
    __shared__ float s_mx[22 * 72];
    __shared__ float s_w[98];
    __shared__ float s_b;

    const int b  = blockIdx.z;
    const int w0 = blockIdx.x * 64;
    const int h0 = blockIdx.y * 16;
    const int tid = threadIdx.x;

    if (tid < 98) s_w[tid] = cw[tid];
    if (tid == 98) s_b = cb[0];

    const float* avgp = g_att + (size_t)b * 2 * HW;
    const float* maxp = avgp + HW;

    for (int i = tid; i < 22 * 70; i += 256) {
        int dy = i / 70, dx = i - dy * 70;
        int hh = h0 - 3 + dy, ww = w0 - 3 + dx;
        float a = 0.f, m = 0.f;
        if (hh >= 0 && hh < 256 && ww >= 0 && ww < 256) {
            int ii = hh * 256 + ww;
            a = avgp[ii];
            m = maxp[ii];
        }
        s_avg[dy * 72 + dx] = a;
        s_mx[dy * 72 + dx]  = m;
    }
    __syncthreads();

    const int tx = tid & 15;
    const int ty = tid >> 4;
    const int ow0 = tx * 4;

    float a0 = s_b, a1 = a0, a2 = a0, a3 = a0;
#pragma unroll
    for (int kh = 0; kh < 7; kh++) {
        const float* ra = s_avg + (ty + kh) * 72 + ow0;
        const float* rm = s_mx  + (ty + kh) * 72 + ow0;
        float v[10];
#pragma unroll
        for (int j = 0; j < 10; j++) v[j] = ra[j];
#pragma unroll
        for (int kw = 0; kw < 7; kw++) {
            float wA = s_w[kh * 7 + kw];
            a0 = fmaf(wA, v[kw],     a0);
            a1 = fmaf(wA, v[kw + 1], a1);
            a2 = fmaf(wA, v[kw + 2], a2);
            a3 = fmaf(wA, v[kw + 3], a3);
        }
#pragma unroll
        for (int j = 0; j < 10; j++) v[j] = rm[j];
#pragma unroll
        for (int kw = 0; kw < 7; kw++) {
            float wM = s_w[49 + kh * 7 + kw];
            a0 = fmaf(wM, v[kw],     a0);
            a1 = fmaf(wM, v[kw + 1], a1);
            a2 = fmaf(wM, v[kw + 2], a2);
            a3 = fmaf(wM, v[kw + 3], a3);
        }
    }
    float4 sg;
    sg.x = 1.0f / (1.0f + __expf(-a0));
    sg.y = 1.0f / (1.0f + __expf(-a1));
    sg.z = 1.0f / (1.0f + __expf(-a2));
    sg.w = 1.0f / (1.0f + __expf(-a3));
    *reinterpret_cast<float4*>(g_s + (size_t)b * HW + (h0 + ty) * 256 + w0 + ow0) = sg;
}

// ---------------------------------------------------------------------------
// K3: out = x * s, channel-reuse mapping.
// Block = 256 consecutive f4-pixels x 16 channels (one s f4 per thread,
// reused 16x). Two batches of 8 channels: 8 independent loads in flight,
// then 8 multiplies + 8 streaming stores. Grid = 16 * 4 * 64 = 4096.
// ---------------------------------------------------------------------------
__global__ void __launch_bounds__(256)
k_mul(const float* __restrict__ x, float* __restrict__ out) {
    const int qblk = blockIdx.x & 63;            // 64 q-tiles of 256 f4
    const int cgrp = (blockIdx.x >> 6) & 3;      // 4 channel groups of 16
    const int b    = blockIdx.x >> 8;            // batch

    const int q4 = qblk * 256 + threadIdx.x;     // [0, HWf4)
    const int c0 = cgrp * 16;

    const float4* xb = reinterpret_cast<const float4*>(x)   + ((size_t)b << 20);
    float4*       ob = reinterpret_cast<float4*>(out)       + ((size_t)b << 20);

    const float4 s = __ldg(reinterpret_cast<const float4*>(g_s + (size_t)b * HW) + q4);

#pragma unroll
    for (int it = 0; it < 2; it++) {
        const int cb0 = c0 + it * 8;
        float4 v[8];
#pragma unroll
        for (int j = 0; j < 8; j++)
            v[j] = __ldcs(xb + (size_t)(cb0 + j) * HWf4 + q4);
#pragma unroll
        for (int j = 0; j < 8; j++) {
            v[j].x *= s.x; v[j].y *= s.y; v[j].z *= s.z; v[j].w *= s.w;
            __stcs(ob + (size_t)(cb0 + j) * HWf4 + q4, v[j]);
        }
    }
}

// ---------------------------------------------------------------------------
extern "C" void kernel_launch(void* const* d_in, const int* in_sizes, int n_in,
                              void* d_out, int out_size) {
    const float* x  = (const float*)d_in[0];
    const float* cw = (const float*)d_in[1];
    const float* cb = (const float*)d_in[2];
    float* out = (float*)d_out;

    k_reduce<<<(B * HWf4) / 256, 256>>>(x);

    dim3 g2(4, 16, B);
    k_conv<<<g2, 256>>>(cw, cb);

    k_mul<<<B * 4 * 64, 256>>>(x, out);
}